// round 12
// baseline (speedup 1.0000x reference)
#include <cuda_runtime.h>
#include <cstdint>
#include <math.h>

// Problem dims
#define NB 512
#define NZ 64
#define NH 256
#define NG 768   // 3*H
#define NT 64
#define NP 10000
#define NPAD 10112          // NP padded to 128
#define MTOT (NB * NT)      // 32768

#define AS_STRIDE 268
#define WS_STRIDE 260
#define GRU_SMEM ((32 * AS_STRIDE + 96 * WS_STRIDE) * 4)

// GEMM: 256x128 tile, swizzled 32-float rows, 3 cp.async stages
// stage = A(256 rows) + B(128 rows), 32 floats/row -> 48 KB; 3 stages = 144 KB
#define GEMM_SMEM (3 * (256 + 128) * 32 * 4)

// ---------------- scratch (device globals; no allocations allowed) ----------
__device__ float g_h0[NB * NH];
__device__ float g_g0[NG];
__device__ float g_st0[2][NB * NH];
__device__ float g_st1[2][NB * NH];
__device__ float g_y0[MTOT * NH];            // layer0 outputs, tf32, K-permuted
__device__ float g_gx1[(size_t)MTOT * NG];
__device__ float g_y1[MTOT * NH];            // layer1 outputs (fp32, pre-LN)
__device__ float g_act[MTOT * NH];           // post LN+ELU, tf32, K-permuted
__device__ float g_Wih1c[NG * NH];           // tf32, K-permuted
__device__ float g_Woutc[NPAD * NH];         // tf32, K-permuted, zero padded
__device__ unsigned g_cnt2[2][NT][16];       // per-(layer,t,batch-tile) barrier

// ---------------- helpers ----------------------------------------------------
__device__ __forceinline__ float f2tf32(float f) {
    uint32_t u;
    asm("cvt.rna.tf32.f32 %0, %1;" : "=r"(u) : "f"(f));
    return __uint_as_float(u);
}

__device__ __forceinline__ int kperm(int k) {
    return (k & ~15) | ((k & 3) << 2) | ((k >> 2) & 3);
}

__device__ __forceinline__ void mma_tf32(float* c, const uint32_t* a, const uint32_t* b) {
    asm volatile(
        "mma.sync.aligned.m16n8k8.row.col.f32.tf32.tf32.f32 "
        "{%0,%1,%2,%3},{%4,%5,%6,%7},{%8,%9},{%0,%1,%2,%3};"
        : "+f"(c[0]), "+f"(c[1]), "+f"(c[2]), "+f"(c[3])
        : "r"(a[0]), "r"(a[1]), "r"(a[2]), "r"(a[3]), "r"(b[0]), "r"(b[1]));
}

__device__ __forceinline__ float sigmoidf_(float x) {
    return 1.f / (1.f + __expf(-x));
}

__device__ __forceinline__ void cp_async16(void* smem_dst, const void* gsrc) {
    unsigned a = (unsigned)__cvta_generic_to_shared(smem_dst);
    asm volatile("cp.async.cg.shared.global [%0], [%1], 16;" :: "r"(a), "l"(gsrc));
}

// ---------------- reset barrier counters -------------------------------------
__global__ void reset_kernel() {
    int i = blockIdx.x * blockDim.x + threadIdx.x;   // 2*64*16 = 2048
    ((unsigned*)g_cnt2)[i] = 0u;
}

// ---------------- prep 1: h0 = ELU(z @ W_init^T + b_init); g0 ---------------
__global__ void prep1_kernel(const float* __restrict__ z,
                             const float* __restrict__ Wi,
                             const float* __restrict__ bi,
                             const float* __restrict__ emb,
                             const float* __restrict__ Wih0,
                             const float* __restrict__ bih0) {
    int blk = blockIdx.x;
    int tid = threadIdx.x;   // 256
    if (blk < NB) {
        __shared__ float zs[NZ];
        if (tid < NZ) zs[tid] = z[blk * NZ + tid];
        __syncthreads();
        float acc = bi[tid];
        #pragma unroll 8
        for (int k = 0; k < NZ; k++) acc = fmaf(zs[k], Wi[tid * NZ + k], acc);
        float h = acc > 0.f ? acc : (expf(acc) - 1.f);
        g_h0[blk * NH + tid] = h;
        g_st0[0][blk * NH + tid] = h;
        g_st1[0][blk * NH + tid] = h;
    } else {
        __shared__ float es[NH];
        es[tid] = emb[tid];
        __syncthreads();
        int g = (blk - NB) * NH + tid;
        float acc = bih0[g];
        #pragma unroll 8
        for (int k = 0; k < NH; k++) acc = fmaf(es[k], Wih0[g * NH + k], acc);
        g_g0[g] = acc;
    }
}

// ---------------- prep: tf32 + K-permuted copies of B matrices ---------------
__global__ void convw_kernel(const float* __restrict__ Wih1,
                             const float* __restrict__ Wout) {
    int idx = blockIdx.x * blockDim.x + threadIdx.x;
    const int n1 = NG * NH;
    const int n2 = NPAD * NH;
    if (idx < n1) {
        int row = idx >> 8, col = idx & 255;
        g_Wih1c[(row << 8) | kperm(col)] = f2tf32(Wih1[idx]);
    }
    for (int j = idx; j < n2; j += gridDim.x * blockDim.x) {
        int row = j >> 8, col = j & 255;
        g_Woutc[(row << 8) | kperm(col)] = (row < NP) ? f2tf32(Wout[j]) : 0.f;
    }
}

// ---------------- persistent GRU layer kernel --------------------------------
__global__ __launch_bounds__(256, 1) void gru_persist_kernel(
    int layer, const float* __restrict__ Whh, const float* __restrict__ bhh) {
    extern __shared__ float smem[];
    float* As = smem;
    float* Ws = smem + 32 * AS_STRIDE;

    const int tid = threadIdx.x;
    const int lane = tid & 31;
    const int warp = tid >> 5;
    const int wm = warp & 1;
    const int wn = warp >> 1;
    const int bb0 = blockIdx.x * 32;
    const int hj0 = blockIdx.y * 32;

    float* st[2];
    if (layer) { st[0] = g_st1[0]; st[1] = g_st1[1]; }
    else       { st[0] = g_st0[0]; st[1] = g_st0[1]; }
    float* ybase = layer ? g_y1 : g_y0;

    #pragma unroll
    for (int i = 0; i < 24; i++) {
        int f = tid + i * 256;
        int rr = f >> 6;
        int c4 = (f & 63) << 2;
        int gate = rr >> 5;
        int r = rr & 31;
        float4 v = *(const float4*)(Whh + (size_t)(gate * NH + hj0 + r) * NH + c4);
        float4 w;
        w.x = f2tf32(v.x); w.y = f2tf32(v.y); w.z = f2tf32(v.z); w.w = f2tf32(v.w);
        *(float4*)(Ws + rr * WS_STRIDE + c4) = w;
    }

    const int r0l = wm * 16 + (lane >> 2);
    const int cl = wn * 8 + (lane & 3) * 2;
    const int jg = hj0 + cl;
    const int pj0 = kperm(jg);
    const int pj1 = kperm(jg + 1);

    const float2 br2 = *(const float2*)(bhh + jg);
    const float2 bz2 = *(const float2*)(bhh + NH + jg);
    const float2 bn2 = *(const float2*)(bhh + 2 * NH + jg);
    float2 x0r, x0z, x0n;
    if (!layer) {
        x0r = *(const float2*)(g_g0 + jg);
        x0z = *(const float2*)(g_g0 + NH + jg);
        x0n = *(const float2*)(g_g0 + 2 * NH + jg);
    }

    const float* aBase = As + (size_t)r0l * AS_STRIDE + (lane & 3);
    const float* bBase = Ws + (size_t)(wn * 8 + (lane >> 2)) * WS_STRIDE + (lane & 3);

    __syncthreads();

    for (int t = 0; t < NT; t++) {
        const float* hc = st[t & 1];
        float* hn_out = st[(t + 1) & 1];

        // ---- prefetch x-gates and h_prev (hide L2 behind the MMA chain) ----
        float2 xr[2], xz[2], xn[2], hp[2];
        #pragma unroll
        for (int rr = 0; rr < 2; rr++) {
            int b = bb0 + r0l + rr * 8;
            if (!layer) { xr[rr] = x0r; xz[rr] = x0z; xn[rr] = x0n; }
            else {
                const float* gxp = g_gx1 + ((size_t)b * NT + t) * NG;
                xr[rr] = *(const float2*)(gxp + jg);
                xz[rr] = *(const float2*)(gxp + NH + jg);
                xn[rr] = *(const float2*)(gxp + 2 * NH + jg);
            }
            hp[rr] = __ldcg((const float2*)(hc + (size_t)b * NH + jg));
        }

        // ---- stage h tile (L2-coherent loads), convert to tf32 ----
        #pragma unroll
        for (int i = 0; i < 8; i++) {
            int f = tid + i * 256;
            int row = f >> 6;
            int c4 = (f & 63) << 2;
            float4 v = __ldcg((const float4*)(hc + (size_t)(bb0 + row) * NH + c4));
            float4 w;
            w.x = f2tf32(v.x); w.y = f2tf32(v.y); w.z = f2tf32(v.z); w.w = f2tf32(v.w);
            *(float4*)(As + row * AS_STRIDE + c4) = w;
        }
        __syncthreads();

        float acc[3][4];
        #pragma unroll
        for (int g = 0; g < 3; g++)
            #pragma unroll
            for (int c = 0; c < 4; c++) acc[g][c] = 0.f;

        #pragma unroll 8
        for (int k = 0; k < NH; k += 8) {
            uint32_t a[4], b[2];
            a[0] = __float_as_uint(aBase[k]);
            a[1] = __float_as_uint(aBase[8 * AS_STRIDE + k]);
            a[2] = __float_as_uint(aBase[k + 4]);
            a[3] = __float_as_uint(aBase[8 * AS_STRIDE + k + 4]);
            #pragma unroll
            for (int g = 0; g < 3; g++) {
                b[0] = __float_as_uint(bBase[g * 32 * WS_STRIDE + k]);
                b[1] = __float_as_uint(bBase[g * 32 * WS_STRIDE + k + 4]);
                mma_tf32(acc[g], a, b);
            }
        }

        // ---- gates + state update; store hn first (the only cross-block dep)
        float2 hv[2];
        #pragma unroll
        for (int rr = 0; rr < 2; rr++) {
            int b = bb0 + r0l + rr * 8;
            float r_0 = sigmoidf_(xr[rr].x + acc[0][rr * 2 + 0] + br2.x);
            float r_1 = sigmoidf_(xr[rr].y + acc[0][rr * 2 + 1] + br2.y);
            float u_0 = sigmoidf_(xz[rr].x + acc[1][rr * 2 + 0] + bz2.x);
            float u_1 = sigmoidf_(xz[rr].y + acc[1][rr * 2 + 1] + bz2.y);
            float n_0 = tanhf(xn[rr].x + r_0 * (acc[2][rr * 2 + 0] + bn2.x));
            float n_1 = tanhf(xn[rr].y + r_1 * (acc[2][rr * 2 + 1] + bn2.y));
            hv[rr].x = (1.f - u_0) * n_0 + u_0 * hp[rr].x;
            hv[rr].y = (1.f - u_1) * n_1 + u_1 * hp[rr].y;
            __stcg((float2*)(hn_out + (size_t)b * NH + jg), hv[rr]);
        }

        // arrive as soon as hn stores are fenced; overlap y-store with
        // other blocks' arrival
        __threadfence();
        __syncthreads();
        if (tid == 0) atomicAdd(&g_cnt2[layer][t][blockIdx.x], 1u);

        #pragma unroll
        for (int rr = 0; rr < 2; rr++) {
            int b = bb0 + r0l + rr * 8;
            float* yrow = ybase + ((size_t)b * NT + t) * NH;
            if (!layer) {
                yrow[pj0] = f2tf32(hv[rr].x);  // K-permuted tf32 for gx1 GEMM
                yrow[pj1] = f2tf32(hv[rr].y);
            } else {
                *(float2*)(yrow + jg) = hv[rr];   // plain (consumed by LN)
            }
        }
        __syncthreads();
        if (tid == 0) {
            volatile unsigned* p = &g_cnt2[layer][t][blockIdx.x];
            while (*p < 8u) { }
        }
        __syncthreads();
    }
}

// ---------------- LayerNorm + ELU (tf32-rounded, K-permuted store) -----------
__global__ void ln_elu_kernel(const float* __restrict__ gam,
                              const float* __restrict__ bet) {
    int row = blockIdx.x;
    int tid = threadIdx.x;
    float v = g_y1[(size_t)row * NH + tid];

    __shared__ float red[8];
    float s = v;
    #pragma unroll
    for (int o = 16; o; o >>= 1) s += __shfl_xor_sync(0xffffffffu, s, o);
    if ((tid & 31) == 0) red[tid >> 5] = s;
    __syncthreads();
    float tot = red[0] + red[1] + red[2] + red[3] + red[4] + red[5] + red[6] + red[7];
    float mu = tot * (1.f / NH);
    __syncthreads();

    float d = v - mu;
    s = d * d;
    #pragma unroll
    for (int o = 16; o; o >>= 1) s += __shfl_xor_sync(0xffffffffu, s, o);
    if ((tid & 31) == 0) red[tid >> 5] = s;
    __syncthreads();
    tot = red[0] + red[1] + red[2] + red[3] + red[4] + red[5] + red[6] + red[7];
    float var = tot * (1.f / NH);

    float yv = d * rsqrtf(var + 1e-5f) * gam[tid] + bet[tid];
    yv = yv > 0.f ? yv : (__expf(yv) - 1.f);
    g_act[(size_t)row * NH + kperm(tid)] = f2tf32(yv);
}

// ---------------- 256x128 3-stage pipelined tf32 GEMM ------------------------
// A: M x 256 (tf32, K-permuted), B: Npad x 256 (tf32, K-permuted).
// 512 threads = 16 warps: wm = warp&3 (64-row slice), wn = warp>>2 (32-col).
// smem stage s at sm + s*12288: A 256x32, B 128x32 (XOR-swizzled rows).
__global__ __launch_bounds__(512, 1) void gemm_pipe_kernel(
    const float* __restrict__ A, const float* __restrict__ Bm,
    const float* __restrict__ bias, float* __restrict__ C, int Nstore) {
    const int K = NH;
    extern __shared__ float sm[];

    const int tid = threadIdx.x;
    const int lane = tid & 31;
    const int warp = tid >> 5;
    const int wm = warp & 3;
    const int wn = warp >> 2;
    const int m0 = blockIdx.y * 256;
    const int n0 = blockIdx.x * 128;

    float acc[4][4][4];
    #pragma unroll
    for (int a = 0; a < 4; a++)
        #pragma unroll
        for (int b = 0; b < 4; b++)
            #pragma unroll
            for (int c = 0; c < 4; c++) acc[a][b][c] = 0.f;

    auto stagef = [&](int kt, int s) {
        const int ko = kt * 32;
        float* dA = sm + s * 12288;
        float* dB = dA + 8192;
        #pragma unroll
        for (int i = 0; i < 6; i++) {
            int idx = i * 512 + tid;             // 0..3071
            if (idx < 2048) {                    // A: 256 rows x 8 chunks
                int r = idx >> 3, ck = idx & 7;
                int pc = ck ^ ((r & 1) << 2);
                cp_async16(dA + r * 32 + pc * 4, A + (size_t)(m0 + r) * K + ko + ck * 4);
            } else {                             // B: 128 rows x 8 chunks
                int j = idx - 2048;
                int r = j >> 3, ck = j & 7;
                int pc = ck ^ ((r & 1) << 2);
                cp_async16(dB + r * 32 + pc * 4, Bm + (size_t)(n0 + r) * K + ko + ck * 4);
            }
        }
        asm volatile("cp.async.commit_group;");
    };

    // prologue: two tiles in flight
    stagef(0, 0);
    stagef(1, 1);

    const int ra = wm * 64 + (lane >> 2);
    const int rb = wn * 32 + (lane >> 2);
    const int c = lane & 3;

    #pragma unroll
    for (int kt = 0; kt < 8; kt++) {
        if (kt < 7) asm volatile("cp.async.wait_group 1;");
        else        asm volatile("cp.async.wait_group 0;");
        __syncthreads();
        if (kt + 2 < 8) stagef(kt + 2, (kt + 2) % 3);

        const float* sAb = sm + (kt % 3) * 12288;
        const float* sBb = sAb + 8192;
        #pragma unroll
        for (int b16 = 0; b16 < 2; b16++) {
            float4 bf[4];
            #pragma unroll
            for (int nf = 0; nf < 4; nf++) {
                int rr = rb + nf * 8;
                int pc = (b16 * 4 + c) ^ ((rr & 1) << 2);
                bf[nf] = *(const float4*)(sBb + rr * 32 + pc * 4);
            }
            #pragma unroll
            for (int mf = 0; mf < 4; mf++) {
                int r0 = ra + mf * 16;
                int pc = (b16 * 4 + c) ^ ((r0 & 1) << 2);
                float4 a0 = *(const float4*)(sAb + r0 * 32 + pc * 4);
                float4 a1 = *(const float4*)(sAb + (r0 + 8) * 32 + pc * 4);
                uint32_t afA[4] = { __float_as_uint(a0.x), __float_as_uint(a1.x),
                                   __float_as_uint(a0.y), __float_as_uint(a1.y) };
                uint32_t afB[4] = { __float_as_uint(a0.z), __float_as_uint(a1.z),
                                   __float_as_uint(a0.w), __float_as_uint(a1.w) };
                #pragma unroll
                for (int nf = 0; nf < 4; nf++) {
                    uint32_t b0[2] = { __float_as_uint(bf[nf].x), __float_as_uint(bf[nf].y) };
                    uint32_t b1[2] = { __float_as_uint(bf[nf].z), __float_as_uint(bf[nf].w) };
                    mma_tf32(acc[mf][nf], afA, b0);
                    mma_tf32(acc[mf][nf], afB, b1);
                }
            }
        }
    }

    // epilogue: add bias, store (guard col < Nstore)
    __syncthreads();
    #pragma unroll
    for (int mf = 0; mf < 4; mf++) {
        int row = m0 + wm * 64 + mf * 16 + (lane >> 2);
        #pragma unroll
        for (int nf = 0; nf < 4; nf++) {
            int col = n0 + wn * 32 + nf * 8 + (lane & 3) * 2;
            if (col < Nstore) {
                float2 bv = *(const float2*)(bias + col);
                float2 o0 = make_float2(acc[mf][nf][0] + bv.x, acc[mf][nf][1] + bv.y);
                float2 o1 = make_float2(acc[mf][nf][2] + bv.x, acc[mf][nf][3] + bv.y);
                *(float2*)(C + (size_t)row * Nstore + col) = o0;
                *(float2*)(C + (size_t)(row + 8) * Nstore + col) = o1;
            }
        }
    }
}

// ---------------- launch -----------------------------------------------------
extern "C" void kernel_launch(void* const* d_in, const int* in_sizes, int n_in,
                              void* d_out, int out_size) {
    const float* z      = (const float*)d_in[0];
    const float* W_init = (const float*)d_in[1];
    const float* b_init = (const float*)d_in[2];
    const float* emb    = (const float*)d_in[3];
    const float* W_ih0  = (const float*)d_in[4];
    const float* W_hh0  = (const float*)d_in[5];
    const float* b_ih0  = (const float*)d_in[6];
    const float* b_hh0  = (const float*)d_in[7];
    const float* W_ih1  = (const float*)d_in[8];
    const float* W_hh1  = (const float*)d_in[9];
    const float* b_ih1  = (const float*)d_in[10];
    const float* b_hh1  = (const float*)d_in[11];
    const float* ln_g   = (const float*)d_in[12];
    const float* ln_b   = (const float*)d_in[13];
    const float* W_out  = (const float*)d_in[14];
    const float* b_out  = (const float*)d_in[15];
    float* out = (float*)d_out;

    static bool attr_done = false;
    if (!attr_done) {
        cudaFuncSetAttribute(gru_persist_kernel,
                             cudaFuncAttributeMaxDynamicSharedMemorySize, GRU_SMEM);
        cudaFuncSetAttribute(gemm_pipe_kernel,
                             cudaFuncAttributeMaxDynamicSharedMemorySize, GEMM_SMEM);
        attr_done = true;
    }

    float* Wih1c; cudaGetSymbolAddress((void**)&Wih1c, g_Wih1c);
    float* Woutc; cudaGetSymbolAddress((void**)&Woutc, g_Woutc);
    float* y0;    cudaGetSymbolAddress((void**)&y0, g_y0);
    float* act;   cudaGetSymbolAddress((void**)&act, g_act);
    float* gx1;   cudaGetSymbolAddress((void**)&gx1, g_gx1);

    reset_kernel<<<8, 256>>>();
    prep1_kernel<<<NB + 3, 256>>>(z, W_init, b_init, emb, W_ih0, b_ih0);
    convw_kernel<<<2720, 256>>>(W_ih1, W_out);

    // GRU layer 0 (persistent)
    gru_persist_kernel<<<dim3(16, 8), 256, GRU_SMEM>>>(0, W_hh0, b_hh0);

    // gx1 = Y0 @ W_ih1^T + b_ih1
    gemm_pipe_kernel<<<dim3(NG / 128, MTOT / 256), 512, GEMM_SMEM>>>(
        y0, Wih1c, b_ih1, gx1, NG);

    // GRU layer 1 (persistent)
    gru_persist_kernel<<<dim3(16, 8), 256, GRU_SMEM>>>(1, W_hh1, b_hh1);

    // LayerNorm + ELU
    ln_elu_kernel<<<MTOT, 256>>>(ln_g, ln_b);

    // logits = act @ W_out^T + b_out
    gemm_pipe_kernel<<<dim3(NPAD / 128, MTOT / 256), 512, GEMM_SMEM>>>(
        act, Woutc, b_out, out, NP);
}